// round 4
// baseline (speedup 1.0000x reference)
#include <cuda_runtime.h>

#define BB 4
#define CC 256
#define HH 64
#define WW 96
#define ND 21
#define CBK 4
#define NCH 64
#define HW (HH * WW)
#define CSTRIDE (CBK * HW)

// smem geometry (float units), channel-quad layout [..][slot][cc0..3]
#define S2P  304          // in2 parity pitch (76 slots * 4)
#define S2D  612          // in2 V-row pitch  (153*4 ; 153 % 8 == 1 -> l-distinct banks)
#define S2B  4896         // 8 V-rows per buffer
#define S1P  224          // in1 parity pitch (56 slots * 4)
#define S1R  448          // in1 y-row pitch
#define S1B  896
#define BUFSZ (S2B + S1B) // 5792 floats per buffer
#define SM1OFF S2B

// Block: (dyg in [0,3), yp in [0,32), b). y0 = 4*(yp>>1) + (yp&1); rows y0 and y0+2.
// 288 threads: tid -> dxg=tid/96, pxg=(tid%96)>>3, l=(tid%96)&7  (l fastest -> uniform phases).
// Thread: pixels x=16g+2k+p (k<8), dx block 7*dxg+j (j<7), V row m=l shared by
//   (y0, dyl=7dyg+l) and (y0+2, dyl=7dyg+l-1)  -> 2 rows per V window.
__global__ __launch_bounds__(288, 1)
void corr_kernel(const float* __restrict__ in1, const float* __restrict__ in2,
                 float* __restrict__ out) {
    const int dyg = blockIdx.x;
    const int yp  = blockIdx.y;
    const int b   = blockIdx.z;
    const int y0  = 4 * (yp >> 1) + (yp & 1);

    __shared__ __align__(16) float SM[2 * BUFSZ];

    const int tid = threadIdx.x;
    // zero both buffers once; halo / OOB rows / swizzle gaps stay zero forever
    for (int i = tid; i < 2 * BUFSZ; i += 288) SM[i] = 0.f;

    // ---- staging roles: threads 0..239 handle 4 positions each (960 = 768 in2 + 192 in1)
    const float* gp[4];
    int so[4];                                     // smem offset in buffer, or -1
    if (tid < 240) {
#pragma unroll
        for (int js = 0; js < 4; js++) {
            int pidx = tid + 240 * js;
            if (pidx < 768) {                      // in2: row m, position x2
                int m  = pidx / 96;
                int x2 = pidx - 96 * m;
                int yy = y0 + 14 * dyg + 2 * m - 20;
                bool v = ((unsigned)yy < (unsigned)HH);
                gp[js] = in2 + ((size_t)b * CC) * HW + yy * WW + x2;
                int pos = (x2 >> 1) + 10;
                int sg  = pos + (pos >> 3);
                so[js]  = v ? (m * S2D + (x2 & 1) * S2P + sg * 4) : -1;
            } else {                               // in1: row yr (y0 or y0+2), position x
                int rem = pidx - 768;
                int yr  = rem / 96;
                int x   = rem - 96 * yr;
                gp[js] = in1 + ((size_t)b * CC) * HW + (y0 + 2 * yr) * WW + x;
                int pos = x >> 1;
                int sg  = pos + (pos >> 3);
                so[js]  = SM1OFF + yr * S1R + (x & 1) * S1P + sg * 4;
            }
        }
    } else {
#pragma unroll
        for (int js = 0; js < 4; js++) { gp[js] = in1; so[js] = -1; }
    }

    // ---- compute roles ----
    const int dxg = tid / 96;
    const int r96 = tid - 96 * dxg;
    const int pxg = r96 >> 3;
    const int l   = r96 & 7;
    const int g   = pxg >> 1;
    const int p   = pxg & 1;
    const int pos0 = 8 * g + 7 * dxg;              // V position base

    float4 pf[4];
    auto do_ldg = [&]() {
#pragma unroll
        for (int js = 0; js < 4; js++) {
            if (so[js] >= 0) {
                const float* q = gp[js];
                pf[js] = make_float4(q[0], q[HW], q[2 * HW], q[3 * HW]);
            }
            gp[js] += CSTRIDE;
        }
    };
    auto do_sts = [&](int bsel) {
        float* base = SM + bsel * BUFSZ;
#pragma unroll
        for (int js = 0; js < 4; js++)
            if (so[js] >= 0) *(float4*)(base + so[js]) = pf[js];
    };

    float accY[56], accZ[56];
#pragma unroll
    for (int i = 0; i < 56; i++) { accY[i] = 0.f; accZ[i] = 0.f; }

    __syncthreads();              // zeroing complete before first STS
    do_ldg();
    do_sts(0);
    __syncthreads();

#pragma unroll 1
    for (int k = 0; k < NCH; k++) {
        const bool pre = (k + 1 < NCH);
        if (pre) do_ldg();

        const float* buf = SM + (k & 1) * BUFSZ;
        const float* Vb = buf + l * S2D + p * S2P;
        float4 V[14];
#pragma unroll
        for (int t = 0; t < 14; t++) {
            int pos = pos0 + t;
            int sg  = pos + (pos >> 3);
            V[t] = *(const float4*)(Vb + 4 * sg);
        }
        const float* Ab = buf + SM1OFF + p * S1P;
#pragma unroll
        for (int kk = 0; kk < 8; kk++) {
            int sgk = 4 * (9 * g + kk);
            float4 ay = *(const float4*)(Ab + sgk);          // row y0   (broadcast)
            float4 az = *(const float4*)(Ab + S1R + sgk);    // row y0+2 (broadcast)
#pragma unroll
            for (int j = 0; j < 7; j++) {
                float4 v = V[kk + j];
                float ty = accY[j * 8 + kk];
                ty = fmaf(ay.x, v.x, ty); ty = fmaf(ay.y, v.y, ty);
                ty = fmaf(ay.z, v.z, ty); ty = fmaf(ay.w, v.w, ty);
                accY[j * 8 + kk] = ty;
                float tz = accZ[j * 8 + kk];
                tz = fmaf(az.x, v.x, tz); tz = fmaf(az.y, v.y, tz);
                tz = fmaf(az.z, v.z, tz); tz = fmaf(az.w, v.w, tz);
                accZ[j * 8 + kk] = tz;
            }
        }

        if (pre) do_sts((k & 1) ^ 1);
        __syncthreads();
    }

    // ---- epilogue ----
    const float scale = 1.f / 256.f;
    const int xb = 16 * g + p;
    if (l <= 6) {                                  // row y0, dyl = 7dyg+l
        int dyi = 7 * dyg + l;
        for (int j = 0; j < 7; j++) {
            int d = dyi * ND + 7 * dxg + j;
            float* op = out + (((size_t)b * ND * ND + d) * HH + y0) * WW + xb;
#pragma unroll
            for (int kk = 0; kk < 8; kk++)
                op[2 * kk] = accY[j * 8 + kk] * scale;
        }
    }
    if (l >= 1) {                                  // row y0+2, dyl = 7dyg+l-1
        int dyi = 7 * dyg + l - 1;
        for (int j = 0; j < 7; j++) {
            int d = dyi * ND + 7 * dxg + j;
            float* op = out + (((size_t)b * ND * ND + d) * HH + (y0 + 2)) * WW + xb;
#pragma unroll
            for (int kk = 0; kk < 8; kk++)
                op[2 * kk] = accZ[j * 8 + kk] * scale;
        }
    }
}

extern "C" void kernel_launch(void* const* d_in, const int* in_sizes, int n_in,
                              void* d_out, int out_size) {
    const float* in1 = (const float*)d_in[0];
    const float* in2 = (const float*)d_in[1];
    float* out = (float*)d_out;
    dim3 grid(3, 32, BB);
    corr_kernel<<<grid, 288>>>(in1, in2, out);
}